// round 5
// baseline (speedup 1.0000x reference)
#include <cuda_runtime.h>

#define K_TOTAL 100000
#define KC      256
#define NB      ((K_TOTAL + KC - 1) / KC)   // 391
#define SEQ     64
#define G4      200                          // 4*H
#define HID     50
#define SG      (SEQ * G4)                   // 12800

#define RGROUPS 16
#define RSPAN   25

#define WSTAGE  8
#define WBUFS   4

// Scratch (device globals)
__device__ float g_partial[NB * SG];
__device__ float g_p2[RGROUPS * SG];

typedef unsigned long long ull;

__device__ __forceinline__ ull pack2(float a, float b) {
    ull r; asm("mov.b64 %0, {%1, %2};" : "=l"(r) : "f"(a), "f"(b)); return r;
}
__device__ __forceinline__ ull packdup(float a) {
    ull r; asm("mov.b64 %0, {%1, %1};" : "=l"(r) : "f"(a)); return r;
}
__device__ __forceinline__ void fma2(ull& d, ull a, ull b) {
    asm("fma.rn.f32x2 %0, %1, %2, %0;" : "+l"(d) : "l"(a), "l"(b));
}
__device__ __forceinline__ float lo32(ull v) { return __uint_as_float((unsigned)(v & 0xffffffffu)); }
__device__ __forceinline__ float hi32(ull v) { return __uint_as_float((unsigned)(v >> 32)); }

__device__ __forceinline__ void cp_async16(float* smem, const float* gmem) {
    unsigned sa = (unsigned)__cvta_generic_to_shared(smem);
    asm volatile("cp.async.cg.shared.global [%0], [%1], 16;" :: "r"(sa), "l"(gmem));
}
__device__ __forceinline__ void cp_commit() { asm volatile("cp.async.commit_group;"); }
__device__ __forceinline__ void cp_wait2() { asm volatile("cp.async.wait_group 2;"); }
__device__ __forceinline__ void cp_wait1() { asm volatile("cp.async.wait_group 1;"); }
__device__ __forceinline__ void cp_wait0() { asm volatile("cp.async.wait_group 0;"); }

// ---------------------------------------------------------------------------
// Phase A: split-K GEMM. 200 threads, 8g x 8s register tile (32 fma2 / j-row).
// thread t: gq8 = t%25 (gate cols 8gq8..+7), sh8 = t/25 (s = 8sh8..+7).
// Wi staged via cp.async into split-dense float4 arrays: ws4[stage][jj][h][gq8].
// ---------------------------------------------------------------------------
__global__ void __launch_bounds__(200, 2) gemm_partial(
    const float* __restrict__ x, const float* __restrict__ Wi)
{
    extern __shared__ float sm[];
    float*  xs   = sm;                  // KC*64 floats (64 KB), [j][s-pairs] swizzled
    float4* wsf4 = (float4*)(sm + KC * 64);   // WBUFS*400 float4 (25.6 KB)
    const int t  = threadIdx.x;
    const int k0 = blockIdx.x * KC;

    // ---- stage x chunk: 4s x 4j register transpose, swizzled STS.128 ----
    for (int tile = t; tile < (KC / 4) * 16; tile += 200) {
        const int tj = tile & (KC / 4 - 1);
        const int ts = tile >> 6;
        const int jg = tj * 4;
        float4 rv[4];
        #pragma unroll
        for (int u = 0; u < 4; u++) {
            const int s  = ts * 4 + u;
            const int gj = k0 + jg;
            const float* px = x + (size_t)s * K_TOTAL + gj;
            if (gj + 3 < K_TOTAL) {
                rv[u] = *(const float4*)px;
            } else {
                float a = (gj + 0 < K_TOTAL) ? px[0] : 0.f;
                float b = (gj + 1 < K_TOTAL) ? px[1] : 0.f;
                float c = (gj + 2 < K_TOTAL) ? px[2] : 0.f;
                float d = (gj + 3 < K_TOTAL) ? px[3] : 0.f;
                rv[u] = make_float4(a, b, c, d);
            }
        }
        const float* rf = reinterpret_cast<const float*>(rv);
        #pragma unroll
        for (int v = 0; v < 4; v++) {
            const int j    = jg + v;
            const int idx4 = j * 16 + (ts ^ (j & 15));
            *(float4*)(xs + idx4 * 4) =
                make_float4(rf[0 * 4 + v], rf[1 * 4 + v], rf[2 * 4 + v], rf[3 * 4 + v]);
        }
    }

    const int gq8 = t % 25;
    const int sh8 = t / 25;              // 0..7
    const int q0  = (2 * sh8) & 15;
    const int q1  = q0 + 1;

    const int rem    = K_TOTAL - k0;
    const int jend   = rem < KC ? rem : KC;   // 256 or 160, % 8 == 0
    const int stages = jend / WSTAGE;

    // cp.async slot decomposition (2 slots/thread, 400 slots/stage)
    const int s2a = t, s2b = t + 200;
    const int jjA = s2a / 50, remA = s2a % 50, hA = remA / 25, gA = remA % 25;
    const int jjB = s2b / 50, remB = s2b % 50, hB = remB / 25, gB = remB % 25;
    const float* srcA = Wi + (size_t)(k0 + jjA) * G4 + gA * 8 + hA * 4;
    const float* srcB = Wi + (size_t)(k0 + jjB) * G4 + gB * 8 + hB * 4;
    const int dstA = jjA * 50 + hA * 25 + gA;
    const int dstB = jjB * 50 + hB * 25 + gB;

    // prime stages 0, 1
    #pragma unroll
    for (int ps = 0; ps < 2; ps++) {
        cp_async16((float*)(wsf4 + (ps % WBUFS) * 400 + dstA),
                   srcA + (size_t)(ps * WSTAGE) * G4);
        cp_async16((float*)(wsf4 + (ps % WBUFS) * 400 + dstB),
                   srcB + (size_t)(ps * WSTAGE) * G4);
        cp_commit();
    }

    ull acc[8][4];
    #pragma unroll
    for (int a = 0; a < 8; a++)
        #pragma unroll
        for (int b = 0; b < 4; b++) acc[a][b] = 0ull;

    __syncthreads();   // covers xs staging

    for (int s = 0; s < stages; s++) {
        if (s + 2 < stages) {
            cp_async16((float*)(wsf4 + ((s + 2) % WBUFS) * 400 + dstA),
                       srcA + (size_t)((s + 2) * WSTAGE) * G4);
            cp_async16((float*)(wsf4 + ((s + 2) % WBUFS) * 400 + dstB),
                       srcB + (size_t)((s + 2) * WSTAGE) * G4);
            cp_commit();
            cp_wait2();
        } else if (s + 1 < stages) {
            cp_wait1();
        } else {
            cp_wait0();
        }
        __syncthreads();

        const float4* wl = wsf4 + (s % WBUFS) * 400;
        const int jb = s * WSTAGE;
        #pragma unroll
        for (int jj = 0; jj < WSTAGE; jj++) {
            const int j  = jb + jj;
            const int jm = j & 15;
            const int jbase = j * 16;
            const float4 wa = wl[jj * 50 + gq8];        // gate cols 8g..8g+3 (dense)
            const float4 wb = wl[jj * 50 + 25 + gq8];   // gate cols 8g+4..+7 (dense)
            const ulonglong2 xa = *(const ulonglong2*)(xs + (jbase + (q0 ^ jm)) * 4);
            const ulonglong2 xb = *(const ulonglong2*)(xs + (jbase + (q1 ^ jm)) * 4);
            const ull xp0 = xa.x, xp1 = xa.y, xp2 = xb.x, xp3 = xb.y;
            const float wv[8] = {wa.x, wa.y, wa.z, wa.w, wb.x, wb.y, wb.z, wb.w};
            #pragma unroll
            for (int g = 0; g < 8; g++) {
                const ull wpg = packdup(wv[g]);
                fma2(acc[g][0], xp0, wpg);
                fma2(acc[g][1], xp1, wpg);
                fma2(acc[g][2], xp2, wpg);
                fma2(acc[g][3], xp3, wpg);
            }
        }
    }

    float* pout = g_partial + (size_t)blockIdx.x * SG;
    #pragma unroll
    for (int p = 0; p < 4; p++) {
        const int sE = sh8 * 8 + 2 * p;
        float* base = pout + (size_t)sE * G4 + gq8 * 8;
        *(float4*)(base)           = make_float4(lo32(acc[0][p]), lo32(acc[1][p]), lo32(acc[2][p]), lo32(acc[3][p]));
        *(float4*)(base + 4)       = make_float4(lo32(acc[4][p]), lo32(acc[5][p]), lo32(acc[6][p]), lo32(acc[7][p]));
        *(float4*)(base + G4)      = make_float4(hi32(acc[0][p]), hi32(acc[1][p]), hi32(acc[2][p]), hi32(acc[3][p]));
        *(float4*)(base + G4 + 4)  = make_float4(hi32(acc[4][p]), hi32(acc[5][p]), hi32(acc[6][p]), hi32(acc[7][p]));
    }
}

// ---------------------------------------------------------------------------
// Phase B: stage-1 split-K reduce (stage 2 merged into lstm preload)
// ---------------------------------------------------------------------------
__global__ void reduce_stage1()
{
    const int idx = blockIdx.x * blockDim.x + threadIdx.x;
    const int grp = blockIdx.y;
    if (idx >= SG) return;
    const int b0   = grp * RSPAN;
    const int bend = (b0 + RSPAN < NB) ? (b0 + RSPAN) : NB;
    float s0 = 0.f, s1 = 0.f, s2 = 0.f, s3 = 0.f;
    int b = b0;
    for (; b + 3 < bend; b += 4) {
        s0 += g_partial[(size_t)(b + 0) * SG + idx];
        s1 += g_partial[(size_t)(b + 1) * SG + idx];
        s2 += g_partial[(size_t)(b + 2) * SG + idx];
        s3 += g_partial[(size_t)(b + 3) * SG + idx];
    }
    for (; b < bend; b++) s0 += g_partial[(size_t)b * SG + idx];
    g_p2[(size_t)grp * SG + idx] = (s0 + s1) + (s2 + s3);
}

// ---------------------------------------------------------------------------
// Phase C: LSTM, 64 threads, thread-per-hidden-unit, 1 barrier/step,
// double-buffered h, merged final reduce + bias in preload.
// ---------------------------------------------------------------------------
__device__ __forceinline__ float tanh_fast(float v) {
    float r; asm("tanh.approx.f32 %0, %1;" : "=f"(r) : "f"(v)); return r;
}
__device__ __forceinline__ float sig_fast(float v) {
    return fmaf(0.5f, tanh_fast(0.5f * v), 0.5f);
}

__global__ void __launch_bounds__(64) lstm_kernel(const float* __restrict__ Wh,
                                                  const float* __restrict__ bi,
                                                  const float* __restrict__ bh,
                                                  float* __restrict__ out)
{
    extern __shared__ float sml[];
    float* gates_s = sml;                         // SG floats (51.2 KB)
    ull*   wf_s    = (ull*)(sml + SG);            // 25*50 ull (10 KB)
    ull*   wg_s    = wf_s + 25 * 50;
    ull*   wo_s    = wg_s + 25 * 50;
    float* bsum_s  = (float*)(wo_s + 25 * 50);    // 200 floats
    float* hbuf    = bsum_s + 200;                // 2 x 64 floats (double buffer)
    const int t = threadIdx.x;

    // bias sums
    for (int i = t; i < G4; i += 64) bsum_s[i] = bi[i] + bh[i];
    if (t < 25 * 2) { ((ull*)hbuf)[t] = 0ull; ((ull*)(hbuf + 64))[t] = 0ull; }
    __syncthreads();

    // merged reduce_stage2: sum 16 partials + bias -> gates_s
    {
        const float4* src = (const float4*)g_p2;
        float4* dst = (float4*)gates_s;
        for (int i4 = t; i4 < SG / 4; i4 += 64) {
            float4 a0 = make_float4(0.f, 0.f, 0.f, 0.f);
            float4 a1 = a0, a2 = a0, a3 = a0;
            #pragma unroll
            for (int b = 0; b < RGROUPS; b += 4) {
                float4 v0 = src[(size_t)(b + 0) * (SG / 4) + i4];
                float4 v1 = src[(size_t)(b + 1) * (SG / 4) + i4];
                float4 v2 = src[(size_t)(b + 2) * (SG / 4) + i4];
                float4 v3 = src[(size_t)(b + 3) * (SG / 4) + i4];
                a0.x += v0.x; a0.y += v0.y; a0.z += v0.z; a0.w += v0.w;
                a1.x += v1.x; a1.y += v1.y; a1.z += v1.z; a1.w += v1.w;
                a2.x += v2.x; a2.y += v2.y; a2.z += v2.z; a2.w += v2.w;
                a3.x += v3.x; a3.y += v3.y; a3.z += v3.z; a3.w += v3.w;
            }
            const float4 bsv = *(const float4*)(bsum_s + (i4 * 4) % G4);
            float4 r;
            r.x = (a0.x + a1.x) + (a2.x + a3.x) + bsv.x;
            r.y = (a0.y + a1.y) + (a2.y + a3.y) + bsv.y;
            r.z = (a0.z + a1.z) + (a2.z + a3.z) + bsv.z;
            r.w = (a0.w + a1.w) + (a2.w + a3.w) + bsv.w;
            dst[i4] = r;
        }
    }

    // pack recurrent weights: gate f/g/o into smem (dense [k2*50 + j]), gate i in regs
    for (int e = t; e < 25 * 50; e += 64) {
        const int k2 = e / 50, j = e % 50;
        wf_s[e] = pack2(Wh[(2 * k2) * G4 +  50 + j], Wh[(2 * k2 + 1) * G4 +  50 + j]);
        wg_s[e] = pack2(Wh[(2 * k2) * G4 + 100 + j], Wh[(2 * k2 + 1) * G4 + 100 + j]);
        wo_s[e] = pack2(Wh[(2 * k2) * G4 + 150 + j], Wh[(2 * k2 + 1) * G4 + 150 + j]);
    }
    ull wp_i[25];
    if (t < HID) {
        #pragma unroll
        for (int k2 = 0; k2 < 25; k2++)
            wp_i[k2] = pack2(Wh[(2 * k2) * G4 + t], Wh[(2 * k2 + 1) * G4 + t]);
    }
    float c = 0.f, hlast = 0.f;
    __syncthreads();

    for (int step = 0; step < SEQ; step++) {
        if (t < HID) {
            const float* hb = hbuf + (step & 1) * 64;
            const ull* hu = (const ull*)hb;
            const float pre_i = gates_s[step * G4 + t];
            const float pre_f = gates_s[step * G4 +  50 + t];
            const float pre_g = gates_s[step * G4 + 100 + t];
            const float pre_o = gates_s[step * G4 + 150 + t];
            ull ai = 0ull, af = 0ull, ag = 0ull, ao = 0ull;
            #pragma unroll
            for (int k2 = 0; k2 < 25; k2++) {
                const ull hp = hu[k2];
                fma2(ai, hp, wp_i[k2]);
                fma2(af, hp, wf_s[k2 * 50 + t]);
                fma2(ag, hp, wg_s[k2 * 50 + t]);
                fma2(ao, hp, wo_s[k2 * 50 + t]);
            }
            const float iv = sig_fast(pre_i + lo32(ai) + hi32(ai));
            const float fv = sig_fast(pre_f + lo32(af) + hi32(af));
            const float gv = tanh_fast(pre_g + lo32(ag) + hi32(ag));
            const float ov = sig_fast(pre_o + lo32(ao) + hi32(ao));
            c = fv * c + iv * gv;
            hlast = ov * tanh_fast(c);
            hbuf[((step + 1) & 1) * 64 + t] = hlast;   // write NEW buffer
        }
        __syncthreads();                                // single barrier per step
    }
    if (t < HID) out[t] = hlast;
}

// ---------------------------------------------------------------------------
extern "C" void kernel_launch(void* const* d_in, const int* in_sizes, int n_in,
                              void* d_out, int out_size)
{
    const float* x  = (const float*)d_in[0];
    const float* Wi = (const float*)d_in[1];
    const float* bi = (const float*)d_in[2];
    const float* Wh = (const float*)d_in[3];
    const float* bh = (const float*)d_in[4];
    float* out = (float*)d_out;

    (void)in_sizes; (void)n_in; (void)out_size;

    const int gemm_smem = (KC * 64) * 4 + WBUFS * 400 * 16;   // 64KB + 25.6KB
    cudaFuncSetAttribute(gemm_partial, cudaFuncAttributeMaxDynamicSharedMemorySize,
                         gemm_smem);
    const int lstm_smem = SG * 4 + 3 * 25 * 50 * 8 + 200 * 4 + 2 * 64 * 4 + 64;
    cudaFuncSetAttribute(lstm_kernel, cudaFuncAttributeMaxDynamicSharedMemorySize,
                         lstm_smem);

    gemm_partial<<<NB, 200, gemm_smem>>>(x, Wi);
    reduce_stage1<<<dim3(SG / 128, RGROUPS), 128>>>();
    lstm_kernel<<<1, 64, lstm_smem>>>(Wh, bi, bh, out);
}

// round 6
// speedup vs baseline: 1.1339x; 1.1339x over previous
#include <cuda_runtime.h>

#define K_TOTAL 100000
#define KC      176
#define NB      ((K_TOTAL + KC - 1) / KC)   // 569
#define SEQ     64
#define G4      200                          // 4*H
#define HID     50
#define SG      (SEQ * G4)                   // 12800

#define RGROUPS 16
#define RSPAN   36                            // 16*36 = 576 >= 569

#define WSTAGE  8
#define WBUFS   4

// Scratch (device globals)
__device__ float g_partial[NB * SG];          // ~29 MB
__device__ float g_p2[RGROUPS * SG];

typedef unsigned long long ull;

__device__ __forceinline__ ull pack2(float a, float b) {
    ull r; asm("mov.b64 %0, {%1, %2};" : "=l"(r) : "f"(a), "f"(b)); return r;
}
__device__ __forceinline__ ull packdup(float a) {
    ull r; asm("mov.b64 %0, {%1, %1};" : "=l"(r) : "f"(a)); return r;
}
__device__ __forceinline__ void fma2(ull& d, ull a, ull b) {
    asm("fma.rn.f32x2 %0, %1, %2, %0;" : "+l"(d) : "l"(a), "l"(b));
}
__device__ __forceinline__ float lo32(ull v) { return __uint_as_float((unsigned)(v & 0xffffffffu)); }
__device__ __forceinline__ float hi32(ull v) { return __uint_as_float((unsigned)(v >> 32)); }

__device__ __forceinline__ void cp_async16(float* smem, const float* gmem) {
    unsigned sa = (unsigned)__cvta_generic_to_shared(smem);
    asm volatile("cp.async.cg.shared.global [%0], [%1], 16;" :: "r"(sa), "l"(gmem));
}
__device__ __forceinline__ void cp_commit() { asm volatile("cp.async.commit_group;"); }
__device__ __forceinline__ void cp_wait2() { asm volatile("cp.async.wait_group 2;"); }
__device__ __forceinline__ void cp_wait1() { asm volatile("cp.async.wait_group 1;"); }
__device__ __forceinline__ void cp_wait0() { asm volatile("cp.async.wait_group 0;"); }

// ---------------------------------------------------------------------------
// Phase A: split-K GEMM. 200 threads, 8g x 8s tile. KC=176 for wave balance
// (569 chunks / 296 slots -> <=2 chunks per slot, 1.04 tail vs 1.51 at KC=256).
// ---------------------------------------------------------------------------
__global__ void __launch_bounds__(200, 2) gemm_partial(
    const float* __restrict__ x, const float* __restrict__ Wi)
{
    extern __shared__ float sm[];
    float*  xs   = sm;                        // KC*64 floats (45 KB), swizzled
    float4* wsf4 = (float4*)(sm + KC * 64);   // WBUFS*400 float4 (25.6 KB)
    const int t  = threadIdx.x;
    const int k0 = blockIdx.x * KC;

    // ---- stage x chunk: 4s x 4j register transpose, swizzled STS.128 ----
    for (int tile = t; tile < (KC / 4) * 16; tile += 200) {
        const int tj = tile % (KC / 4);
        const int ts = tile / (KC / 4);
        const int jg = tj * 4;
        float4 rv[4];
        #pragma unroll
        for (int u = 0; u < 4; u++) {
            const int s  = ts * 4 + u;
            const int gj = k0 + jg;
            const float* px = x + (size_t)s * K_TOTAL + gj;
            if (gj + 3 < K_TOTAL) {
                rv[u] = *(const float4*)px;
            } else {
                float a = (gj + 0 < K_TOTAL) ? px[0] : 0.f;
                float b = (gj + 1 < K_TOTAL) ? px[1] : 0.f;
                float c = (gj + 2 < K_TOTAL) ? px[2] : 0.f;
                float d = (gj + 3 < K_TOTAL) ? px[3] : 0.f;
                rv[u] = make_float4(a, b, c, d);
            }
        }
        const float* rf = reinterpret_cast<const float*>(rv);
        #pragma unroll
        for (int v = 0; v < 4; v++) {
            const int j    = jg + v;
            const int idx4 = j * 16 + (ts ^ (j & 15));
            *(float4*)(xs + idx4 * 4) =
                make_float4(rf[0 * 4 + v], rf[1 * 4 + v], rf[2 * 4 + v], rf[3 * 4 + v]);
        }
    }

    const int gq8 = t % 25;
    const int sh8 = t / 25;
    const int q0  = (2 * sh8) & 15;
    const int q1  = q0 + 1;

    const int rem    = K_TOTAL - k0;
    const int jend   = rem < KC ? rem : KC;   // 176 or 32 (both % 8 == 0)
    const int stages = jend / WSTAGE;

    // cp.async slot decomposition (2 slots/thread, 400 slots/stage)
    const int s2a = t, s2b = t + 200;
    const int jjA = s2a / 50, remA = s2a % 50, hA = remA / 25, gA = remA % 25;
    const int jjB = s2b / 50, remB = s2b % 50, hB = remB / 25, gB = remB % 25;
    const float* srcA = Wi + (size_t)(k0 + jjA) * G4 + gA * 8 + hA * 4;
    const float* srcB = Wi + (size_t)(k0 + jjB) * G4 + gB * 8 + hB * 4;
    const int dstA = jjA * 50 + hA * 25 + gA;
    const int dstB = jjB * 50 + hB * 25 + gB;

    #pragma unroll
    for (int ps = 0; ps < 2; ps++) {
        if (ps < stages) {
            cp_async16((float*)(wsf4 + (ps % WBUFS) * 400 + dstA),
                       srcA + (size_t)(ps * WSTAGE) * G4);
            cp_async16((float*)(wsf4 + (ps % WBUFS) * 400 + dstB),
                       srcB + (size_t)(ps * WSTAGE) * G4);
        }
        cp_commit();
    }

    ull acc[8][4];
    #pragma unroll
    for (int a = 0; a < 8; a++)
        #pragma unroll
        for (int b = 0; b < 4; b++) acc[a][b] = 0ull;

    __syncthreads();

    for (int s = 0; s < stages; s++) {
        if (s + 2 < stages) {
            cp_async16((float*)(wsf4 + ((s + 2) % WBUFS) * 400 + dstA),
                       srcA + (size_t)((s + 2) * WSTAGE) * G4);
            cp_async16((float*)(wsf4 + ((s + 2) % WBUFS) * 400 + dstB),
                       srcB + (size_t)((s + 2) * WSTAGE) * G4);
            cp_commit();
            cp_wait2();
        } else if (s + 1 < stages) {
            cp_wait1();
        } else {
            cp_wait0();
        }
        __syncthreads();

        const float4* wl = wsf4 + (s % WBUFS) * 400;
        const int jb = s * WSTAGE;
        #pragma unroll
        for (int jj = 0; jj < WSTAGE; jj++) {
            const int j  = jb + jj;
            const int jm = j & 15;
            const int jbase = j * 16;
            const float4 wa = wl[jj * 50 + gq8];
            const float4 wb = wl[jj * 50 + 25 + gq8];
            const ulonglong2 xa = *(const ulonglong2*)(xs + (jbase + (q0 ^ jm)) * 4);
            const ulonglong2 xb = *(const ulonglong2*)(xs + (jbase + (q1 ^ jm)) * 4);
            const ull xp0 = xa.x, xp1 = xa.y, xp2 = xb.x, xp3 = xb.y;
            const float wv[8] = {wa.x, wa.y, wa.z, wa.w, wb.x, wb.y, wb.z, wb.w};
            #pragma unroll
            for (int g = 0; g < 8; g++) {
                const ull wpg = packdup(wv[g]);
                fma2(acc[g][0], xp0, wpg);
                fma2(acc[g][1], xp1, wpg);
                fma2(acc[g][2], xp2, wpg);
                fma2(acc[g][3], xp3, wpg);
            }
        }
    }

    float* pout = g_partial + (size_t)blockIdx.x * SG;
    #pragma unroll
    for (int p = 0; p < 4; p++) {
        const int sE = sh8 * 8 + 2 * p;
        float* base = pout + (size_t)sE * G4 + gq8 * 8;
        *(float4*)(base)           = make_float4(lo32(acc[0][p]), lo32(acc[1][p]), lo32(acc[2][p]), lo32(acc[3][p]));
        *(float4*)(base + 4)       = make_float4(lo32(acc[4][p]), lo32(acc[5][p]), lo32(acc[6][p]), lo32(acc[7][p]));
        *(float4*)(base + G4)      = make_float4(hi32(acc[0][p]), hi32(acc[1][p]), hi32(acc[2][p]), hi32(acc[3][p]));
        *(float4*)(base + G4 + 4)  = make_float4(hi32(acc[4][p]), hi32(acc[5][p]), hi32(acc[6][p]), hi32(acc[7][p]));
    }
}

// ---------------------------------------------------------------------------
// Phase B: stage-1 split-K reduce (569 -> 16)
// ---------------------------------------------------------------------------
__global__ void reduce_stage1()
{
    const int idx = blockIdx.x * blockDim.x + threadIdx.x;
    const int grp = blockIdx.y;
    if (idx >= SG) return;
    const int b0   = grp * RSPAN;
    const int bend = (b0 + RSPAN < NB) ? (b0 + RSPAN) : NB;
    float s0 = 0.f, s1 = 0.f, s2 = 0.f, s3 = 0.f;
    int b = b0;
    for (; b + 3 < bend; b += 4) {
        s0 += g_partial[(size_t)(b + 0) * SG + idx];
        s1 += g_partial[(size_t)(b + 1) * SG + idx];
        s2 += g_partial[(size_t)(b + 2) * SG + idx];
        s3 += g_partial[(size_t)(b + 3) * SG + idx];
    }
    for (; b < bend; b++) s0 += g_partial[(size_t)b * SG + idx];
    g_p2[(size_t)grp * SG + idx] = (s0 + s1) + (s2 + s3);
}

// ---------------------------------------------------------------------------
// Phase C: LSTM. 256 threads: all 8 warps do the 16-way reduce + bias into
// smem; warps 0-1 run the thread-per-unit recurrence (1 barrier/step).
// ---------------------------------------------------------------------------
__device__ __forceinline__ float tanh_fast(float v) {
    float r; asm("tanh.approx.f32 %0, %1;" : "=f"(r) : "f"(v)); return r;
}
__device__ __forceinline__ float sig_fast(float v) {
    return fmaf(0.5f, tanh_fast(0.5f * v), 0.5f);
}

__global__ void __launch_bounds__(256) lstm_kernel(const float* __restrict__ Wh,
                                                   const float* __restrict__ bi,
                                                   const float* __restrict__ bh,
                                                   float* __restrict__ out)
{
    extern __shared__ float sml[];
    float* gates_s = sml;                         // SG floats (51.2 KB)
    ull*   wf_s    = (ull*)(sml + SG);            // 3 x 25*50 ull (30 KB)
    ull*   wg_s    = wf_s + 25 * 50;
    ull*   wo_s    = wg_s + 25 * 50;
    float* hbuf    = (float*)(wo_s + 25 * 50);    // 2 x 64 floats
    const int t = threadIdx.x;

    // merged reduce_stage2 + bias: 8 warps, float4, MLP=16
    {
        const float4* src = (const float4*)g_p2;
        float4* dst = (float4*)gates_s;
        for (int i4 = t; i4 < SG / 4; i4 += 256) {
            float4 a0 = make_float4(0.f, 0.f, 0.f, 0.f);
            float4 a1 = a0, a2 = a0, a3 = a0;
            #pragma unroll
            for (int b = 0; b < RGROUPS; b += 4) {
                float4 v0 = src[(size_t)(b + 0) * (SG / 4) + i4];
                float4 v1 = src[(size_t)(b + 1) * (SG / 4) + i4];
                float4 v2 = src[(size_t)(b + 2) * (SG / 4) + i4];
                float4 v3 = src[(size_t)(b + 3) * (SG / 4) + i4];
                a0.x += v0.x; a0.y += v0.y; a0.z += v0.z; a0.w += v0.w;
                a1.x += v1.x; a1.y += v1.y; a1.z += v1.z; a1.w += v1.w;
                a2.x += v2.x; a2.y += v2.y; a2.z += v2.z; a2.w += v2.w;
                a3.x += v3.x; a3.y += v3.y; a3.z += v3.z; a3.w += v3.w;
            }
            const int gbase = (i4 * 4) % G4;
            const float4 bv1 = *(const float4*)(bi + gbase);
            const float4 bv2 = *(const float4*)(bh + gbase);
            float4 r;
            r.x = (a0.x + a1.x) + (a2.x + a3.x) + bv1.x + bv2.x;
            r.y = (a0.y + a1.y) + (a2.y + a3.y) + bv1.y + bv2.y;
            r.z = (a0.z + a1.z) + (a2.z + a3.z) + bv1.z + bv2.z;
            r.w = (a0.w + a1.w) + (a2.w + a3.w) + bv1.w + bv2.w;
            dst[i4] = r;
        }
    }

    // pack recurrent weights (f/g/o to smem, i to regs of t<50)
    for (int e = t; e < 25 * 50; e += 256) {
        const int k2 = e / 50, j = e % 50;
        wf_s[e] = pack2(Wh[(2 * k2) * G4 +  50 + j], Wh[(2 * k2 + 1) * G4 +  50 + j]);
        wg_s[e] = pack2(Wh[(2 * k2) * G4 + 100 + j], Wh[(2 * k2 + 1) * G4 + 100 + j]);
        wo_s[e] = pack2(Wh[(2 * k2) * G4 + 150 + j], Wh[(2 * k2 + 1) * G4 + 150 + j]);
    }
    ull wp_i[25];
    if (t < HID) {
        #pragma unroll
        for (int k2 = 0; k2 < 25; k2++)
            wp_i[k2] = pack2(Wh[(2 * k2) * G4 + t], Wh[(2 * k2 + 1) * G4 + t]);
    }
    if (t < 64) { hbuf[t] = 0.f; hbuf[64 + t] = 0.f; }
    float c = 0.f, hlast = 0.f;
    __syncthreads();

    for (int step = 0; step < SEQ; step++) {
        if (t < HID) {
            const ull* hu = (const ull*)(hbuf + (step & 1) * 64);
            const float pre_i = gates_s[step * G4 + t];
            const float pre_f = gates_s[step * G4 +  50 + t];
            const float pre_g = gates_s[step * G4 + 100 + t];
            const float pre_o = gates_s[step * G4 + 150 + t];
            ull ai = 0ull, af = 0ull, ag = 0ull, ao = 0ull;
            #pragma unroll
            for (int k2 = 0; k2 < 25; k2++) {
                const ull hp = hu[k2];
                fma2(ai, hp, wp_i[k2]);
                fma2(af, hp, wf_s[k2 * 50 + t]);
                fma2(ag, hp, wg_s[k2 * 50 + t]);
                fma2(ao, hp, wo_s[k2 * 50 + t]);
            }
            const float iv = sig_fast(pre_i + lo32(ai) + hi32(ai));
            const float fv = sig_fast(pre_f + lo32(af) + hi32(af));
            const float gv = tanh_fast(pre_g + lo32(ag) + hi32(ag));
            const float ov = sig_fast(pre_o + lo32(ao) + hi32(ao));
            c = fv * c + iv * gv;
            hlast = ov * tanh_fast(c);
            hbuf[((step + 1) & 1) * 64 + t] = hlast;
        }
        __syncthreads();
    }
    if (t < HID) out[t] = hlast;
}

// ---------------------------------------------------------------------------
extern "C" void kernel_launch(void* const* d_in, const int* in_sizes, int n_in,
                              void* d_out, int out_size)
{
    const float* x  = (const float*)d_in[0];
    const float* Wi = (const float*)d_in[1];
    const float* bi = (const float*)d_in[2];
    const float* Wh = (const float*)d_in[3];
    const float* bh = (const float*)d_in[4];
    float* out = (float*)d_out;

    (void)in_sizes; (void)n_in; (void)out_size;

    const int gemm_smem = (KC * 64) * 4 + WBUFS * 400 * 16;   // 45KB + 25.6KB
    cudaFuncSetAttribute(gemm_partial, cudaFuncAttributeMaxDynamicSharedMemorySize,
                         gemm_smem);
    const int lstm_smem = SG * 4 + 3 * 25 * 50 * 8 + 2 * 64 * 4 + 64;
    cudaFuncSetAttribute(lstm_kernel, cudaFuncAttributeMaxDynamicSharedMemorySize,
                         lstm_smem);

    gemm_partial<<<NB, 200, gemm_smem>>>(x, Wi);
    reduce_stage1<<<dim3(SG / 128, RGROUPS), 128>>>();
    lstm_kernel<<<1, 256, lstm_smem>>>(Wh, bi, bh, out);
}

// round 7
// speedup vs baseline: 1.6853x; 1.4864x over previous
#include <cuda_runtime.h>
#include <cstdint>

#define K_TOTAL 100000
#define KC      704
#define NB      143                           // 142*704 + 32 = 100000 exactly
#define KB      32                            // k per pipeline step
#define SEQ     64
#define G4      200
#define HID     50
#define SG      (SEQ * G4)                    // 12800

#define RGROUPS 16
#define RSPAN   9                             // 16*9 = 144 >= 143

// Scratch (device globals)
__device__ float g_partial[NB * SG];          // 7.3 MB
__device__ float g_p2[RGROUPS * SG];

typedef unsigned long long ull;

__device__ __forceinline__ ull pack2(float a, float b) {
    ull r; asm("mov.b64 %0, {%1, %2};" : "=l"(r) : "f"(a), "f"(b)); return r;
}
__device__ __forceinline__ void fma2(ull& d, ull a, ull b) {
    asm("fma.rn.f32x2 %0, %1, %2, %0;" : "+l"(d) : "l"(a), "l"(b));
}
__device__ __forceinline__ ull add2(ull a, ull b) {
    ull r; asm("add.rn.f32x2 %0, %1, %2;" : "=l"(r) : "l"(a), "l"(b)); return r;
}
__device__ __forceinline__ float lo32(ull v) { return __uint_as_float((unsigned)(v & 0xffffffffu)); }
__device__ __forceinline__ float hi32(ull v) { return __uint_as_float((unsigned)(v >> 32)); }

__device__ __forceinline__ void cp_async16(float* smem, const float* gmem) {
    unsigned sa = (unsigned)__cvta_generic_to_shared(smem);
    asm volatile("cp.async.cg.shared.global [%0], [%1], 16;" :: "r"(sa), "l"(gmem));
}
__device__ __forceinline__ void cp_commit() { asm volatile("cp.async.commit_group;"); }
__device__ __forceinline__ void cp_wait1() { asm volatile("cp.async.wait_group 1;"); }

// pack two f32 into bf16x2: hi_val -> bits[31:16], lo_val -> bits[15:0]
__device__ __forceinline__ uint32_t cvtpack(float hi_val, float lo_val) {
    uint32_t r;
    asm("cvt.rn.bf16x2.f32 %0, %1, %2;" : "=r"(r) : "f"(hi_val), "f"(lo_val));
    return r;
}

__device__ __forceinline__ void mma16816(float* d,
                                         uint32_t a0, uint32_t a1, uint32_t a2, uint32_t a3,
                                         uint32_t b0, uint32_t b1) {
    asm volatile(
        "mma.sync.aligned.m16n8k16.row.col.f32.bf16.bf16.f32 "
        "{%0,%1,%2,%3}, {%4,%5,%6,%7}, {%8,%9}, {%0,%1,%2,%3};"
        : "+f"(d[0]), "+f"(d[1]), "+f"(d[2]), "+f"(d[3])
        : "r"(a0), "r"(a1), "r"(a2), "r"(a3), "r"(b0), "r"(b1));
}

// permuted slot within a k16 block: places (tq, tq+4) k2-pairs adjacent for LDS.64
__device__ __forceinline__ int mslot(int k2) {
    return ((k2 >> 3) << 3) + 2 * (k2 & 3) + ((k2 & 7) >> 2);
}

// ---------------------------------------------------------------------------
// Phase A: split-K tensor-core GEMM (bf16 split precision, 3 combos).
// 143 CTAs x 256 threads, 3-stage cp.async fp32 staging, 2-buf bf16 conversion.
// ---------------------------------------------------------------------------
__global__ void __launch_bounds__(256, 1) gemm_partial(
    const float* __restrict__ x, const float* __restrict__ Wi)
{
    extern __shared__ float sm[];
    float* stgX = sm;                                     // 3 x 64x32 f32
    float* stgW = sm + 3 * 2048;                          // 3 x 32x200 f32
    uint32_t* cXh = (uint32_t*)(sm + 3 * 2048 + 3 * 6400); // 2 x 64x18 b32
    uint32_t* cXl = cXh + 2 * 1152;
    uint32_t* cWh = cXl + 2 * 1152;                       // 2 x 200x18 b32
    uint32_t* cWl = cWh + 2 * 3600;

    const int t  = threadIdx.x;
    const int k0 = blockIdx.x * KC;
    const int kcnt = (K_TOTAL - k0 < KC) ? (K_TOTAL - k0) : KC;
    const int S = kcnt / KB;                              // 22 or 1

    const int warp = t >> 5, lane = t & 31;
    const int g = lane >> 2, tq = lane & 3;
    const int mpair = warp >> 2;                          // 0..1 (rows 32*mpair..+31)
    const int nq = warp & 3;
    const int ncnt = (nq == 0) ? 7 : 6;
    const int nbeg = (nq == 0) ? 0 : 7 + 6 * (nq - 1);

    float acc[2][7][4];
    #pragma unroll
    for (int a = 0; a < 2; a++)
        #pragma unroll
        for (int b = 0; b < 7; b++)
            #pragma unroll
            for (int c = 0; c < 4; c++) acc[a][b][c] = 0.f;

    // ---- stage issue (fp32 tiles via cp.async) ----
    auto issue_stage = [&](int step, int b3) {
        const int kg = k0 + step * KB;
        float* dX = stgX + b3 * 2048;
        float* dW = stgW + b3 * 6400;
        const float* sW = Wi + (size_t)kg * G4;           // 32x200 contiguous
        for (int i = t; i < 1600; i += 256)
            cp_async16(dW + i * 4, sW + (size_t)i * 4);
        for (int i = t; i < 512; i += 256) {
            const int row = i >> 3, q = i & 7;
            cp_async16(dX + row * 32 + q * 4, x + (size_t)row * K_TOTAL + kg + q * 4);
        }
    };

    // ---- fp32 -> bf16 hi/lo split conversion ----
    auto convert = [&](int b3, int b2) {
        const float* sX = stgX + b3 * 2048;
        const float* sW = stgW + b3 * 6400;
        uint32_t* xh = cXh + b2 * 1152; uint32_t* xl = cXl + b2 * 1152;
        uint32_t* wh = cWh + b2 * 3600; uint32_t* wl = cWl + b2 * 3600;
        for (int p = t; p < 3200; p += 256) {             // W: 200n x 16 k-pairs
            const int k2 = p / 200, n = p % 200;
            const float f0 = sW[(2 * k2) * 200 + n];
            const float f1 = sW[(2 * k2 + 1) * 200 + n];
            const uint32_t hi = cvtpack(f1, f0);
            const float h0 = __uint_as_float(hi << 16);
            const float h1 = __uint_as_float(hi & 0xFFFF0000u);
            const uint32_t lo = cvtpack(f1 - h1, f0 - h0);
            const int ms = mslot(k2);
            wh[n * 18 + ms] = hi;
            wl[n * 18 + ms] = lo;
        }
        for (int p = t; p < 1024; p += 256) {             // X: 64 rows x 16 k-pairs
            const int k2 = p & 15, row = p >> 4;
            const float f0 = sX[row * 32 + 2 * k2];
            const float f1 = sX[row * 32 + 2 * k2 + 1];
            const uint32_t hi = cvtpack(f1, f0);
            const float h0 = __uint_as_float(hi << 16);
            const float h1 = __uint_as_float(hi & 0xFFFF0000u);
            const uint32_t lo = cvtpack(f1 - h1, f0 - h0);
            const int ms = mslot(k2);
            xh[row * 18 + ms] = hi;
            xl[row * 18 + ms] = lo;
        }
    };

    // ---- mma over one converted KB tile ----
    auto mma_tile = [&](int b2) {
        const uint32_t* xh = cXh + b2 * 1152; const uint32_t* xl = cXl + b2 * 1152;
        const uint32_t* wh = cWh + b2 * 3600; const uint32_t* wl = cWl + b2 * 3600;
        #pragma unroll
        for (int kb = 0; kb < 16; kb += 8) {              // two k16 sub-steps
            uint2 Ah[2][2], Al[2][2];
            #pragma unroll
            for (int mt = 0; mt < 2; mt++) {
                const int r0 = (mpair * 2 + mt) * 16 + g;
                Ah[mt][0] = *(const uint2*)(xh + r0 * 18 + kb + 2 * tq);
                Ah[mt][1] = *(const uint2*)(xh + (r0 + 8) * 18 + kb + 2 * tq);
                Al[mt][0] = *(const uint2*)(xl + r0 * 18 + kb + 2 * tq);
                Al[mt][1] = *(const uint2*)(xl + (r0 + 8) * 18 + kb + 2 * tq);
            }
            #pragma unroll
            for (int i = 0; i < 7; i++) {
                if (i < ncnt) {
                    const int n = (nbeg + i) * 8 + g;
                    const uint2 Bh = *(const uint2*)(wh + n * 18 + kb + 2 * tq);
                    const uint2 Bl = *(const uint2*)(wl + n * 18 + kb + 2 * tq);
                    #pragma unroll
                    for (int mt = 0; mt < 2; mt++) {
                        mma16816(acc[mt][i], Ah[mt][0].x, Ah[mt][1].x, Ah[mt][0].y, Ah[mt][1].y, Bh.x, Bh.y);
                        mma16816(acc[mt][i], Ah[mt][0].x, Ah[mt][1].x, Ah[mt][0].y, Ah[mt][1].y, Bl.x, Bl.y);
                        mma16816(acc[mt][i], Al[mt][0].x, Al[mt][1].x, Al[mt][0].y, Al[mt][1].y, Bh.x, Bh.y);
                    }
                }
            }
        }
    };

    // ---- pipeline ----
    issue_stage(0, 0);
    cp_commit();
    if (S > 1) issue_stage(1, 1);
    cp_commit();
    cp_wait1();                 // group 0 done
    __syncthreads();
    convert(0, 0);

    for (int s = 0; s < S; s++) {
        if (s + 2 < S) issue_stage(s + 2, (s + 2) % 3);
        cp_commit();
        cp_wait1();             // group for step s+1 done
        __syncthreads();        // visibility of stage s+1 + conv writes
        if (s + 1 < S) convert((s + 1) % 3, (s + 1) & 1);
        mma_tile(s & 1);
    }

    // ---- epilogue: write partials ----
    float* pout = g_partial + (size_t)blockIdx.x * SG;
    #pragma unroll
    for (int mt = 0; mt < 2; mt++) {
        const int r0 = (mpair * 2 + mt) * 16 + g;
        #pragma unroll
        for (int i = 0; i < 7; i++) {
            if (i < ncnt) {
                const int col = (nbeg + i) * 8 + 2 * tq;
                *(float2*)(pout + (size_t)r0 * G4 + col)       = make_float2(acc[mt][i][0], acc[mt][i][1]);
                *(float2*)(pout + (size_t)(r0 + 8) * G4 + col) = make_float2(acc[mt][i][2], acc[mt][i][3]);
            }
        }
    }
}

// ---------------------------------------------------------------------------
// Phase B: stage-1 split-K reduce (143 -> 16)
// ---------------------------------------------------------------------------
__global__ void reduce_stage1()
{
    const int idx = blockIdx.x * blockDim.x + threadIdx.x;
    const int grp = blockIdx.y;
    if (idx >= SG) return;
    const int b0   = grp * RSPAN;
    const int bend = (b0 + RSPAN < NB) ? (b0 + RSPAN) : NB;
    float s0 = 0.f, s1 = 0.f, s2 = 0.f, s3 = 0.f;
    int b = b0;
    for (; b + 3 < bend; b += 4) {
        s0 += g_partial[(size_t)(b + 0) * SG + idx];
        s1 += g_partial[(size_t)(b + 1) * SG + idx];
        s2 += g_partial[(size_t)(b + 2) * SG + idx];
        s3 += g_partial[(size_t)(b + 3) * SG + idx];
    }
    for (; b < bend; b++) s0 += g_partial[(size_t)b * SG + idx];
    g_p2[(size_t)grp * SG + idx] = (s0 + s1) + (s2 + s3);
}

// ---------------------------------------------------------------------------
// Phase C: LSTM. 256 threads. 8-warp merged reduce + round-4 recurrence
// (200 threads compute gates, 4 independent fma2 chains) + tanh.approx.
// ---------------------------------------------------------------------------
__device__ __forceinline__ float tanh_fast(float v) {
    float r; asm("tanh.approx.f32 %0, %1;" : "=f"(r) : "f"(v)); return r;
}
__device__ __forceinline__ float sig_fast(float v) {
    return fmaf(0.5f, tanh_fast(0.5f * v), 0.5f);
}

__global__ void __launch_bounds__(256) lstm_kernel(const float* __restrict__ Wh,
                                                   const float* __restrict__ bi,
                                                   const float* __restrict__ bh,
                                                   float* __restrict__ out)
{
    extern __shared__ float sml[];
    float* gates_s = sml;                 // SG floats
    float* hbuf    = sml + SG;            // 64 floats (16B aligned)
    float* gbuf    = hbuf + 64;           // 200 floats
    const int t = threadIdx.x;

    // merged reduce (16 partials) + biases -> gates_s
    {
        const float4* src = (const float4*)g_p2;
        float4* dst = (float4*)gates_s;
        for (int i4 = t; i4 < SG / 4; i4 += 256) {
            float4 a0 = make_float4(0.f, 0.f, 0.f, 0.f);
            float4 a1 = a0, a2 = a0, a3 = a0;
            #pragma unroll
            for (int b = 0; b < RGROUPS; b += 4) {
                float4 v0 = src[(size_t)(b + 0) * (SG / 4) + i4];
                float4 v1 = src[(size_t)(b + 1) * (SG / 4) + i4];
                float4 v2 = src[(size_t)(b + 2) * (SG / 4) + i4];
                float4 v3 = src[(size_t)(b + 3) * (SG / 4) + i4];
                a0.x += v0.x; a0.y += v0.y; a0.z += v0.z; a0.w += v0.w;
                a1.x += v1.x; a1.y += v1.y; a1.z += v1.z; a1.w += v1.w;
                a2.x += v2.x; a2.y += v2.y; a2.z += v2.z; a2.w += v2.w;
                a3.x += v3.x; a3.y += v3.y; a3.z += v3.z; a3.w += v3.w;
            }
            const int gbase = (i4 * 4) % G4;
            const float4 bv1 = *(const float4*)(bi + gbase);
            const float4 bv2 = *(const float4*)(bh + gbase);
            float4 r;
            r.x = (a0.x + a1.x) + (a2.x + a3.x) + bv1.x + bv2.x;
            r.y = (a0.y + a1.y) + (a2.y + a3.y) + bv1.y + bv2.y;
            r.z = (a0.z + a1.z) + (a2.z + a3.z) + bv1.z + bv2.z;
            r.w = (a0.w + a1.w) + (a2.w + a3.w) + bv1.w + bv2.w;
            dst[i4] = r;
        }
    }

    ull wp[25];
    if (t < G4) {
        #pragma unroll
        for (int kk = 0; kk < 25; kk++) {
            float w0 = Wh[(2 * kk + 0) * G4 + t];
            float w1 = Wh[(2 * kk + 1) * G4 + t];
            wp[kk] = pack2(w0, w1);
        }
    }
    if (t < 64) hbuf[t] = 0.f;
    float c = 0.f;
    __syncthreads();

    for (int step = 0; step < SEQ; step++) {
        if (t < G4) {
            const float pre = gates_s[step * G4 + t];
            ull a0 = 0ull, a1 = 0ull, a2 = 0ull, a3 = 0ull;
            #pragma unroll
            for (int kk = 0; kk < 24; kk += 4) {
                const ull h0 = *(const ull*)(hbuf + 2 * kk);
                const ull h1 = *(const ull*)(hbuf + 2 * kk + 2);
                const ull h2 = *(const ull*)(hbuf + 2 * kk + 4);
                const ull h3 = *(const ull*)(hbuf + 2 * kk + 6);
                fma2(a0, h0, wp[kk]);
                fma2(a1, h1, wp[kk + 1]);
                fma2(a2, h2, wp[kk + 2]);
                fma2(a3, h3, wp[kk + 3]);
            }
            fma2(a0, *(const ull*)(hbuf + 48), wp[24]);
            const ull s = add2(add2(a0, a1), add2(a2, a3));
            gbuf[t] = pre + lo32(s) + hi32(s);
        }
        __syncthreads();
        if (t < HID) {
            const float iv = sig_fast(gbuf[t]);
            const float fv = sig_fast(gbuf[HID + t]);
            const float gv = tanh_fast(gbuf[2 * HID + t]);
            const float ov = sig_fast(gbuf[3 * HID + t]);
            c = fv * c + iv * gv;
            hbuf[t] = ov * tanh_fast(c);
        }
        __syncthreads();
    }
    if (t < HID) out[t] = hbuf[t];
}

// ---------------------------------------------------------------------------
extern "C" void kernel_launch(void* const* d_in, const int* in_sizes, int n_in,
                              void* d_out, int out_size)
{
    const float* x  = (const float*)d_in[0];
    const float* Wi = (const float*)d_in[1];
    const float* bi = (const float*)d_in[2];
    const float* Wh = (const float*)d_in[3];
    const float* bh = (const float*)d_in[4];
    float* out = (float*)d_out;

    (void)in_sizes; (void)n_in; (void)out_size;

    // stages: 3*(2048+6400) f32 = 101376 B; conv: (2*1152*2 + 2*3600*2) b32 = 76032 B
    const int gemm_smem = (3 * (2048 + 6400)) * 4 + (2 * 1152 * 2 + 2 * 3600 * 2) * 4;
    cudaFuncSetAttribute(gemm_partial, cudaFuncAttributeMaxDynamicSharedMemorySize,
                         gemm_smem);
    const int lstm_smem = (SG + 64 + 200) * 4 + 64;
    cudaFuncSetAttribute(lstm_kernel, cudaFuncAttributeMaxDynamicSharedMemorySize,
                         lstm_smem);

    gemm_partial<<<NB, 256, gemm_smem>>>(x, Wi);
    reduce_stage1<<<dim3(SG / 128, RGROUPS), 128>>>();
    lstm_kernel<<<1, 256, lstm_smem>>>(Wh, bi, bh, out);
}